// round 15
// baseline (speedup 1.0000x reference)
#include <cuda_runtime.h>
#include <math.h>

#define B0 32
#define C0 512
#define HW 4096
#define DC 32
#define NS 16
#define RK 32
#define LL 512

// ---- global scratch (static device arrays; no runtime malloc) ----
__device__ float g_avg[B0 * C0];
__device__ float g_mx[B0 * C0];
__device__ float g_U[B0 * 2 * DC * LL];      // u layout [bk*32+d][l]
__device__ float g_Delta[B0 * 2 * DC * LL];  // post-softplus delta
__device__ float g_Bs[B0 * 2 * LL * NS];     // [bk][l][n]
__device__ float g_Cs[B0 * 2 * LL * NS];     // [bk][l][n]
__device__ float g_yb[B0 * LL];              // atomically accumulated sum_d w*y
__device__ float g_attn[B0 * C0];

__device__ __forceinline__ float gelu_exact(float v) {
    return 0.5f * v * (1.0f + erff(v * 0.70710678118654752f));
}
__device__ __forceinline__ float ex2_fast(float x) {
    float y;
    asm("ex2.approx.ftz.f32 %0, %1;" : "=f"(y) : "f"(x));
    return y;
}
__device__ __forceinline__ float softplus_fast(float a) {
    return fmaxf(a, 0.0f) + __logf(1.0f + __expf(-fabsf(a)));
}

// ============================================================
// K1: avg + max pool (also zeroes g_yb: one float per block).
// ============================================================
__global__ void pool_kernel(const float* __restrict__ x) {
    int bc = blockIdx.x;
    if (threadIdx.x == 0) g_yb[bc] = 0.0f;   // grid == B0*C0 == elems of g_yb
    const float4* xp = (const float4*)(x + (size_t)bc * HW);
    float s = 0.0f, m = -INFINITY;
#pragma unroll
    for (int it = 0; it < 4; it++) {
        int i = it * 256 + threadIdx.x;
        float4 v = xp[i];
        s += (v.x + v.y) + (v.z + v.w);
        m = fmaxf(m, fmaxf(fmaxf(v.x, v.y), fmaxf(v.z, v.w)));
    }
#pragma unroll
    for (int o = 16; o; o >>= 1) {
        s += __shfl_xor_sync(0xffffffffu, s, o);
        m = fmaxf(m, __shfl_xor_sync(0xffffffffu, m, o));
    }
    __shared__ float ss[8], sm[8];
    int w = threadIdx.x >> 5;
    if ((threadIdx.x & 31) == 0) { ss[w] = s; sm[w] = m; }
    __syncthreads();
    if (threadIdx.x == 0) {
        float S = ss[0], M = sm[0];
#pragma unroll
        for (int i = 1; i < 8; i++) { S += ss[i]; M = fmaxf(M, sm[i]); }
        g_avg[bc] = S * (1.0f / (float)HW);
        g_mx[bc] = M;
    }
}

// ============================================================
// K2: prep v3 — PDL: weight load + wfuse before grid sync; adds
//     the D·u contribution (w_cout[d]*Dcs[kd]*u) into g_yb.
// ============================================================
__global__ void __launch_bounds__(256)
prep_kernel(const float* __restrict__ xc_w,
            const float* __restrict__ dtc_w,
            const float* __restrict__ dtc_b,
            const float* __restrict__ w_cin,
            const float* __restrict__ bn_g,
            const float* __restrict__ bn_b,
            const float* __restrict__ bn_m,
            const float* __restrict__ bn_v,
            const float* __restrict__ Dcs,
            const float* __restrict__ w_cout) {
    const int bk = blockIdx.x >> 3;
    const int b = bk >> 1, k = bk & 1;
    const int l0 = (blockIdx.x & 7) << 6;
    const int tid = threadIdx.x;
    const int myl = tid & 63;
    const int og = tid >> 6;           // 0..3
    const int l = l0 + myl;

    __shared__ float sWdt[1024];       // xc_w rows 0..31 ([r][d])
    __shared__ float sWbc[1024];       // xc_w rows 32..63 (B then C)
    __shared__ float sDt[1024];        // dtc_w[k] ([d][r])
    __shared__ float sM[1024];         // fused dtc_w @ xc_w[:RK]
    __shared__ float sU[64 * 33];      // padded u[l][d]
    __shared__ float sBC[64 * 17];     // padded B[l][n]
    __shared__ float sCC[64 * 17];     // padded C[l][n]
    __shared__ float sCin0[32], sCin1[32], sScale[32], sShift[32], sBias[32], sWD[32];

    // ---- pre-sync work: everything independent of pool outputs ----
    for (int i = tid; i < 1024; i += 256) sWdt[i] = xc_w[k * 2048 + i];
    for (int i = tid; i < 1024; i += 256) sWbc[i] = xc_w[k * 2048 + 1024 + i];
    for (int i = tid; i < 1024; i += 256) sDt[i] = dtc_w[k * 1024 + i];
    if (tid < 32) {
        int d = tid;
        sCin0[d] = w_cin[d * 2 + 0];
        sCin1[d] = w_cin[d * 2 + 1];
        float sc = rsqrtf(bn_v[d] + 1e-5f) * bn_g[d];
        sScale[d] = sc;
        sShift[d] = bn_b[d] - bn_m[d] * sc;
        sBias[d] = dtc_b[k * 32 + d];
        sWD[d] = w_cout[d] * Dcs[k * 32 + d];
    }
    __syncthreads();
    for (int e = tid; e < 1024; e += 256) {
        const int d = e >> 5, dd = e & 31;
        float a = 0.0f;
#pragma unroll
        for (int r = 0; r < 32; r++) a += sDt[d * 32 + r] * sWdt[r * 32 + dd];
        sM[e] = a;
    }

    // ---- wait for pool ----
    cudaGridDependencySynchronize();

    // phase 1: u for 8 d's at this thread's l
    const int c = (k == 0) ? l : (511 - l);
    {
        const float av = g_avg[b * 512 + c];
        const float mv = g_mx[b * 512 + c];
#pragma unroll
        for (int i = 0; i < 8; i++) {
            const int d = og * 8 + i;
            float v = sCin0[d] * av + sCin1[d] * mv;
            v = v * sScale[d] + sShift[d];
            v = gelu_exact(v);
            sU[myl * 33 + d] = v;
            g_U[(bk * 32 + d) * LL + l] = v;
        }
    }
    __syncthreads();

    // phase 2: per-thread u in registers, outputs split by og
    float u[32];
#pragma unroll
    for (int d = 0; d < 32; d++) u[d] = sU[myl * 33 + d];

    if (og < 2) {
#pragma unroll
        for (int i = 0; i < 16; i++) {
            const int d = og * 16 + i;
            float a = sBias[d];
#pragma unroll
            for (int dd = 0; dd < 32; dd++) a += u[dd] * sM[d * 32 + dd];
            g_Delta[(bk * 32 + d) * LL + l] = softplus_fast(a);
        }
        if (og == 0) {
            // D·u term of y, folded out of the scan:
            float du = 0.0f;
#pragma unroll
            for (int d = 0; d < 32; d++) du += sWD[d] * u[d];
            atomicAdd(&g_yb[b * 512 + c], du);   // lmap == c
        }
    } else if (og == 2) {
#pragma unroll
        for (int n = 0; n < 16; n++) {
            float a = 0.0f;
#pragma unroll
            for (int d = 0; d < 32; d++) a += u[d] * sWbc[n * 32 + d];
            sBC[myl * 17 + n] = a;
        }
    } else {
#pragma unroll
        for (int n = 0; n < 16; n++) {
            float a = 0.0f;
#pragma unroll
            for (int d = 0; d < 32; d++) a += u[d] * sWbc[(16 + n) * 32 + d];
            sCC[myl * 17 + n] = a;
        }
    }
    __syncthreads();

    const size_t base = ((size_t)bk * 512 + l0) * NS;
    for (int i = tid; i < 1024; i += 256) {
        const int li = i >> 4, ni = i & 15;
        g_Bs[base + i] = sBC[li * 17 + ni];
        g_Cs[base + i] = sCC[li * 17 + ni];
    }
}

// ============================================================
// K3: scan v7 — 512 threads/block, 32 segments x 16 steps.
//     2x warps vs v6 at same instruction count. Kogge-Stone
//     carry: warp w owns state n=w, its 32 lanes = 32 segments.
//     hloc/Pcum form keeps pass 2 fully parallel; one atomic
//     per thread. PDL-synced.
// ============================================================
__global__ void __launch_bounds__(512, 2)
scan_kernel(const float* __restrict__ Ac_logs,
            const float* __restrict__ w_cout) {
    const int tid = threadIdx.x;
    const int lane = tid & 31;
    const int half = lane >> 4;
    const int n = lane & 15;
    const int seg = (tid >> 5) * 2 + half;   // 0..31
    const int g = blockIdx.x;                // 0..2047
    const int kd = g & 63;
    const int k = kd >> 5;
    const int d = kd & 31;
    const int b = g >> 6;
    const int bkn = g >> 5;
    const int l0 = seg * 16;

    // pre-sync work (inputs only)
    const float A = -__expf(Ac_logs[kd * NS + n]);
    const float cA = A * 1.4426950408889634f;
    const float wd = w_cout[d];

    cudaGridDependencySynchronize();

    const float* __restrict__ dp = g_Delta + (size_t)g * LL + l0;
    const float* __restrict__ up = g_U + (size_t)g * LL + l0;
    const float* __restrict__ Bp = g_Bs + (size_t)bkn * (LL * NS) + (size_t)l0 * NS + n;
    const float* __restrict__ Cp = g_Cs + (size_t)bkn * (LL * NS) + (size_t)l0 * NS + n;

    __shared__ float sA[32 * 16], sB[32 * 16], sH[32 * 16];

    float hloc[16], Pcum[16];

    // ---------- pass 1: h_local and cumulative products (16 steps) ----------
    {
        float h = 0.0f, P = 1.0f;
#pragma unroll
        for (int c = 0; c < 2; c++) {
            float dl[8], ul[8], bv[8];
            const float4* dp4 = (const float4*)(dp + c * 8);
            const float4* up4 = (const float4*)(up + c * 8);
#pragma unroll
            for (int q = 0; q < 2; q++) {
                float4 t = dp4[q];
                dl[q * 4] = t.x; dl[q * 4 + 1] = t.y; dl[q * 4 + 2] = t.z; dl[q * 4 + 3] = t.w;
                float4 s = up4[q];
                ul[q * 4] = s.x; ul[q * 4 + 1] = s.y; ul[q * 4 + 2] = s.z; ul[q * 4 + 3] = s.w;
            }
            const float* bc = Bp + (size_t)c * 8 * NS;
#pragma unroll
            for (int j = 0; j < 8; j++) bv[j] = bc[j * 16];  // coalesced across n
#pragma unroll
            for (int j = 0; j < 8; j++) {
                const int jj = c * 8 + j;
                const float dBu = dl[j] * ul[j] * bv[j];
                const float dAj = ex2_fast(dl[j] * cA);
                h = fmaf(dAj, h, dBu);
                P *= dAj;
                hloc[jj] = h;
                Pcum[jj] = P;
            }
        }
        sA[seg * 16 + n] = P;
        sB[seg * 16 + n] = h;
    }
    __syncthreads();

    // ---------- carry: Kogge-Stone, warp w = state n=w, lanes = segments ----
    {
        const int cn = tid >> 5;      // warp id == state n
        const int cs = tid & 31;      // lane == segment
        float Av = sA[cs * 16 + cn];
        float Bv = sB[cs * 16 + cn];
#pragma unroll
        for (int off = 1; off < 32; off <<= 1) {
            float ap = __shfl_up_sync(0xffffffffu, Av, off);
            float bp = __shfl_up_sync(0xffffffffu, Bv, off);
            if (cs >= off) { Bv = fmaf(Av, bp, Bv); Av *= ap; }
        }
        float hin = __shfl_up_sync(0xffffffffu, Bv, 1);
        sH[cs * 16 + cn] = (cs == 0) ? 0.0f : hin;
    }
    __syncthreads();

    // ---------- pass 2: h_l = hloc_l + Pcum_l*h_in; butterfly; 1 atomic ----
    const float h_in = sH[seg * 16 + n];
    const bool b3 = (n & 8) != 0;
    const bool b2 = (n & 4) != 0;
    const bool b1 = (n & 2) != 0;
    const bool b0 = (n & 1) != 0;

    float cv[16];
#pragma unroll
    for (int j = 0; j < 16; j++) cv[j] = Cp[j * 16];  // coalesced across n
#pragma unroll
    for (int j = 0; j < 16; j++)
        cv[j] = fmaf(Pcum[j], h_in, hloc[j]) * cv[j];

    // folded butterfly: lane n ends with sum over states at l = l0 + n
#pragma unroll
    for (int i = 0; i < 8; i++) {
        float mine = b3 ? cv[i + 8] : cv[i];
        float oth  = b3 ? cv[i]     : cv[i + 8];
        cv[i] = mine + __shfl_xor_sync(0xffffffffu, oth, 8);
    }
#pragma unroll
    for (int i = 0; i < 4; i++) {
        float mine = b2 ? cv[i + 4] : cv[i];
        float oth  = b2 ? cv[i]     : cv[i + 4];
        cv[i] = mine + __shfl_xor_sync(0xffffffffu, oth, 4);
    }
#pragma unroll
    for (int i = 0; i < 2; i++) {
        float mine = b1 ? cv[i + 2] : cv[i];
        float oth  = b1 ? cv[i]     : cv[i + 2];
        cv[i] = mine + __shfl_xor_sync(0xffffffffu, oth, 2);
    }
    {
        float mine = b0 ? cv[1] : cv[0];
        float oth  = b0 ? cv[0] : cv[1];
        cv[0] = mine + __shfl_xor_sync(0xffffffffu, oth, 1);
    }
    const int l = l0 + n;
    const int lmap = (k == 0) ? l : (511 - l);
    atomicAdd(&g_yb[b * 512 + lmap], wd * cv[0]);
}

// ============================================================
// K4: gelu + LayerNorm over L per batch -> attn. PDL-synced.
// ============================================================
__global__ void ln_kernel(const float* __restrict__ ln_g,
                          const float* __restrict__ ln_b) {
    const int b = blockIdx.x;
    const int l = threadIdx.x;
    const float lg = ln_g[l];
    const float lb = ln_b[l];
    cudaGridDependencySynchronize();
    const float yb = gelu_exact(g_yb[b * 512 + l]);
    float s = yb, s2 = yb * yb;
#pragma unroll
    for (int o = 16; o; o >>= 1) {
        s += __shfl_xor_sync(0xffffffffu, s, o);
        s2 += __shfl_xor_sync(0xffffffffu, s2, o);
    }
    __shared__ float rs[16], rs2[16];
    __shared__ float smu, srv;
    const int w = l >> 5;
    if ((l & 31) == 0) { rs[w] = s; rs2[w] = s2; }
    __syncthreads();
    if (l == 0) {
        float S = 0.0f, S2 = 0.0f;
#pragma unroll
        for (int i = 0; i < 16; i++) { S += rs[i]; S2 += rs2[i]; }
        float mu = S * (1.0f / 512.0f);
        float var = S2 * (1.0f / 512.0f) - mu * mu;
        smu = mu;
        srv = rsqrtf(var + 1e-5f);
    }
    __syncthreads();
    g_attn[b * 512 + l] = (yb - smu) * srv * lg + lb;
}

// ============================================================
// K5: out v3 — PDL: prefetch x DURING ln, then sync, scale, store.
// ============================================================
__global__ void out_kernel(const float* __restrict__ x, float* __restrict__ out) {
    const int bc = blockIdx.x;
    const float4* __restrict__ xp = (const float4*)x + (size_t)bc * 1024;
    float4* __restrict__ op = (float4*)out + (size_t)bc * 1024;
    float4 v[4];
#pragma unroll
    for (int j = 0; j < 4; j++) v[j] = xp[j * 256 + threadIdx.x];
    cudaGridDependencySynchronize();
    const float a = 1.0f + g_attn[bc];
#pragma unroll
    for (int j = 0; j < 4; j++) {
        v[j].x *= a; v[j].y *= a; v[j].z *= a; v[j].w *= a;
        op[j * 256 + threadIdx.x] = v[j];
    }
}

// ---- host-side PDL launch helper ----
template <typename F, typename... Args>
static inline void launch_pdl(F f, dim3 grid, dim3 block, Args... args) {
    cudaLaunchConfig_t cfg = {};
    cfg.gridDim = grid;
    cfg.blockDim = block;
    cfg.dynamicSmemBytes = 0;
    cfg.stream = 0;
    cudaLaunchAttribute attr[1];
    attr[0].id = cudaLaunchAttributeProgrammaticStreamSerialization;
    attr[0].val.programmaticStreamSerializationAllowed = 1;
    cfg.attrs = attr;
    cfg.numAttrs = 1;
    cudaLaunchKernelEx(&cfg, f, args...);
}

extern "C" void kernel_launch(void* const* d_in, const int* in_sizes, int n_in,
                              void* d_out, int out_size) {
    const float* x      = (const float*)d_in[0];
    const float* xc_w   = (const float*)d_in[1];
    const float* dtc_w  = (const float*)d_in[2];
    const float* dtc_b  = (const float*)d_in[3];
    const float* Ac     = (const float*)d_in[4];
    const float* Dcs    = (const float*)d_in[5];
    const float* w_cin  = (const float*)d_in[6];
    const float* bn_g   = (const float*)d_in[7];
    const float* bn_b   = (const float*)d_in[8];
    const float* bn_m   = (const float*)d_in[9];
    const float* bn_v   = (const float*)d_in[10];
    const float* w_cout = (const float*)d_in[11];
    const float* ln_g   = (const float*)d_in[12];
    const float* ln_b   = (const float*)d_in[13];

    pool_kernel<<<B0 * C0, 256>>>(x);
    launch_pdl(prep_kernel, dim3(B0 * 2 * 8), dim3(256),
               xc_w, dtc_w, dtc_b, w_cin, bn_g, bn_b, bn_m, bn_v, Dcs, w_cout);
    launch_pdl(scan_kernel, dim3(2048), dim3(512), Ac, w_cout);
    launch_pdl(ln_kernel, dim3(B0), dim3(512), ln_g, ln_b);
    launch_pdl(out_kernel, dim3(B0 * C0), dim3(256), x, (float*)d_out);
}

// round 16
// speedup vs baseline: 1.0172x; 1.0172x over previous
#include <cuda_runtime.h>
#include <math.h>

#define B0 32
#define C0 512
#define HW 4096
#define DC 32
#define NS 16
#define RK 32
#define LL 512

// ---- global scratch (static device arrays; no runtime malloc) ----
__device__ float g_avg[B0 * C0];
__device__ float g_mx[B0 * C0];
__device__ float g_U[B0 * 2 * DC * LL];      // u layout [bk*32+d][l]
__device__ float g_Delta[B0 * 2 * DC * LL];  // post-softplus delta
__device__ float g_Bs[B0 * 2 * LL * NS];     // [bk][l][n]
__device__ float g_Cs[B0 * 2 * LL * NS];     // [bk][l][n]
__device__ float g_yb[B0 * LL];              // atomically accumulated sum_d w*y
__device__ float g_attn[B0 * C0];

__device__ __forceinline__ float gelu_exact(float v) {
    return 0.5f * v * (1.0f + erff(v * 0.70710678118654752f));
}
__device__ __forceinline__ float ex2_fast(float x) {
    float y;
    asm("ex2.approx.ftz.f32 %0, %1;" : "=f"(y) : "f"(x));
    return y;
}
__device__ __forceinline__ float softplus_fast(float a) {
    return fmaxf(a, 0.0f) + __logf(1.0f + __expf(-fabsf(a)));
}

// ============================================================
// K1: avg + max pool (also zeroes g_yb: one float per block).
// ============================================================
__global__ void pool_kernel(const float* __restrict__ x) {
    int bc = blockIdx.x;
    if (threadIdx.x == 0) g_yb[bc] = 0.0f;   // grid == B0*C0 == elems of g_yb
    const float4* xp = (const float4*)(x + (size_t)bc * HW);
    float s = 0.0f, m = -INFINITY;
#pragma unroll
    for (int it = 0; it < 4; it++) {
        int i = it * 256 + threadIdx.x;
        float4 v = xp[i];
        s += (v.x + v.y) + (v.z + v.w);
        m = fmaxf(m, fmaxf(fmaxf(v.x, v.y), fmaxf(v.z, v.w)));
    }
#pragma unroll
    for (int o = 16; o; o >>= 1) {
        s += __shfl_xor_sync(0xffffffffu, s, o);
        m = fmaxf(m, __shfl_xor_sync(0xffffffffu, m, o));
    }
    __shared__ float ss[8], sm[8];
    int w = threadIdx.x >> 5;
    if ((threadIdx.x & 31) == 0) { ss[w] = s; sm[w] = m; }
    __syncthreads();
    if (threadIdx.x == 0) {
        float S = ss[0], M = sm[0];
#pragma unroll
        for (int i = 1; i < 8; i++) { S += ss[i]; M = fmaxf(M, sm[i]); }
        g_avg[bc] = S * (1.0f / (float)HW);
        g_mx[bc] = M;
    }
}

// ============================================================
// K2: prep v3 — PDL: weight load + wfuse before grid sync; adds
//     the D·u contribution (w_cout[d]*Dcs[kd]*u) into g_yb.
// ============================================================
__global__ void __launch_bounds__(256)
prep_kernel(const float* __restrict__ xc_w,
            const float* __restrict__ dtc_w,
            const float* __restrict__ dtc_b,
            const float* __restrict__ w_cin,
            const float* __restrict__ bn_g,
            const float* __restrict__ bn_b,
            const float* __restrict__ bn_m,
            const float* __restrict__ bn_v,
            const float* __restrict__ Dcs,
            const float* __restrict__ w_cout) {
    const int bk = blockIdx.x >> 3;
    const int b = bk >> 1, k = bk & 1;
    const int l0 = (blockIdx.x & 7) << 6;
    const int tid = threadIdx.x;
    const int myl = tid & 63;
    const int og = tid >> 6;           // 0..3
    const int l = l0 + myl;

    __shared__ float sWdt[1024];       // xc_w rows 0..31 ([r][d])
    __shared__ float sWbc[1024];       // xc_w rows 32..63 (B then C)
    __shared__ float sDt[1024];        // dtc_w[k] ([d][r])
    __shared__ float sM[1024];         // fused dtc_w @ xc_w[:RK]
    __shared__ float sU[64 * 33];      // padded u[l][d]
    __shared__ float sBC[64 * 17];     // padded B[l][n]
    __shared__ float sCC[64 * 17];     // padded C[l][n]
    __shared__ float sCin0[32], sCin1[32], sScale[32], sShift[32], sBias[32], sWD[32];

    // ---- pre-sync work: everything independent of pool outputs ----
    for (int i = tid; i < 1024; i += 256) sWdt[i] = xc_w[k * 2048 + i];
    for (int i = tid; i < 1024; i += 256) sWbc[i] = xc_w[k * 2048 + 1024 + i];
    for (int i = tid; i < 1024; i += 256) sDt[i] = dtc_w[k * 1024 + i];
    if (tid < 32) {
        int d = tid;
        sCin0[d] = w_cin[d * 2 + 0];
        sCin1[d] = w_cin[d * 2 + 1];
        float sc = rsqrtf(bn_v[d] + 1e-5f) * bn_g[d];
        sScale[d] = sc;
        sShift[d] = bn_b[d] - bn_m[d] * sc;
        sBias[d] = dtc_b[k * 32 + d];
        sWD[d] = w_cout[d] * Dcs[k * 32 + d];
    }
    __syncthreads();
    for (int e = tid; e < 1024; e += 256) {
        const int d = e >> 5, dd = e & 31;
        float a = 0.0f;
#pragma unroll
        for (int r = 0; r < 32; r++) a += sDt[d * 32 + r] * sWdt[r * 32 + dd];
        sM[e] = a;
    }

    // ---- wait for pool ----
    cudaGridDependencySynchronize();

    // phase 1: u for 8 d's at this thread's l
    const int c = (k == 0) ? l : (511 - l);
    {
        const float av = g_avg[b * 512 + c];
        const float mv = g_mx[b * 512 + c];
#pragma unroll
        for (int i = 0; i < 8; i++) {
            const int d = og * 8 + i;
            float v = sCin0[d] * av + sCin1[d] * mv;
            v = v * sScale[d] + sShift[d];
            v = gelu_exact(v);
            sU[myl * 33 + d] = v;
            g_U[(bk * 32 + d) * LL + l] = v;
        }
    }
    __syncthreads();

    // phase 2: per-thread u in registers, outputs split by og
    float u[32];
#pragma unroll
    for (int d = 0; d < 32; d++) u[d] = sU[myl * 33 + d];

    if (og < 2) {
#pragma unroll
        for (int i = 0; i < 16; i++) {
            const int d = og * 16 + i;
            float a = sBias[d];
#pragma unroll
            for (int dd = 0; dd < 32; dd++) a += u[dd] * sM[d * 32 + dd];
            g_Delta[(bk * 32 + d) * LL + l] = softplus_fast(a);
        }
        if (og == 0) {
            // D·u term of y, folded out of the scan:
            float du = 0.0f;
#pragma unroll
            for (int d = 0; d < 32; d++) du += sWD[d] * u[d];
            atomicAdd(&g_yb[b * 512 + c], du);   // lmap == c
        }
    } else if (og == 2) {
#pragma unroll
        for (int n = 0; n < 16; n++) {
            float a = 0.0f;
#pragma unroll
            for (int d = 0; d < 32; d++) a += u[d] * sWbc[n * 32 + d];
            sBC[myl * 17 + n] = a;
        }
    } else {
#pragma unroll
        for (int n = 0; n < 16; n++) {
            float a = 0.0f;
#pragma unroll
            for (int d = 0; d < 32; d++) a += u[d] * sWbc[(16 + n) * 32 + d];
            sCC[myl * 17 + n] = a;
        }
    }
    __syncthreads();

    const size_t base = ((size_t)bk * 512 + l0) * NS;
    for (int i = tid; i < 1024; i += 256) {
        const int li = i >> 4, ni = i & 15;
        g_Bs[base + i] = sBC[li * 17 + ni];
        g_Cs[base + i] = sCC[li * 17 + ni];
    }
}

// ============================================================
// K3: scan v7b — 512 threads/block, 32 segments x 16 steps.
//     Fixes vs v7: (a) pass 2 folds C into hloc IN PLACE (live
//     regs ~50 < 64 cap, no spill); (b) carry smem padded to
//     stride 17 (conflict-free Kogge-Stone). PDL-synced.
// ============================================================
__global__ void __launch_bounds__(512, 2)
scan_kernel(const float* __restrict__ Ac_logs,
            const float* __restrict__ w_cout) {
    const int tid = threadIdx.x;
    const int lane = tid & 31;
    const int half = lane >> 4;
    const int n = lane & 15;
    const int seg = (tid >> 5) * 2 + half;   // 0..31
    const int g = blockIdx.x;                // 0..2047
    const int kd = g & 63;
    const int k = kd >> 5;
    const int d = kd & 31;
    const int b = g >> 6;
    const int bkn = g >> 5;
    const int l0 = seg * 16;

    // pre-sync work (inputs only)
    const float A = -__expf(Ac_logs[kd * NS + n]);
    const float cA = A * 1.4426950408889634f;
    const float wd = w_cout[d];

    cudaGridDependencySynchronize();

    const float* __restrict__ dp = g_Delta + (size_t)g * LL + l0;
    const float* __restrict__ up = g_U + (size_t)g * LL + l0;
    const float* __restrict__ Bp = g_Bs + (size_t)bkn * (LL * NS) + (size_t)l0 * NS + n;
    const float* __restrict__ Cp = g_Cs + (size_t)bkn * (LL * NS) + (size_t)l0 * NS + n;

    __shared__ float sA[32 * 17], sB[32 * 17], sH[32 * 17];  // padded: stride 17

    float hloc[16], Pcum[16];

    // ---------- pass 1: h_local and cumulative products (16 steps) ----------
    {
        float h = 0.0f, P = 1.0f;
#pragma unroll
        for (int c = 0; c < 2; c++) {
            float dl[8], ul[8], bv[8];
            const float4* dp4 = (const float4*)(dp + c * 8);
            const float4* up4 = (const float4*)(up + c * 8);
#pragma unroll
            for (int q = 0; q < 2; q++) {
                float4 t = dp4[q];
                dl[q * 4] = t.x; dl[q * 4 + 1] = t.y; dl[q * 4 + 2] = t.z; dl[q * 4 + 3] = t.w;
                float4 s = up4[q];
                ul[q * 4] = s.x; ul[q * 4 + 1] = s.y; ul[q * 4 + 2] = s.z; ul[q * 4 + 3] = s.w;
            }
            const float* bc = Bp + (size_t)c * 8 * NS;
#pragma unroll
            for (int j = 0; j < 8; j++) bv[j] = bc[j * 16];  // coalesced across n
#pragma unroll
            for (int j = 0; j < 8; j++) {
                const int jj = c * 8 + j;
                const float dBu = dl[j] * ul[j] * bv[j];
                const float dAj = ex2_fast(dl[j] * cA);
                h = fmaf(dAj, h, dBu);
                P *= dAj;
                hloc[jj] = h;
                Pcum[jj] = P;
            }
        }
        sA[seg * 17 + n] = P;
        sB[seg * 17 + n] = h;
    }
    __syncthreads();

    // ---------- carry: Kogge-Stone, warp w = state n=w, lanes = segments ----
    {
        const int cn = tid >> 5;      // warp id == state n
        const int cs = tid & 31;      // lane == segment
        float Av = sA[cs * 17 + cn];  // stride 17: conflict-free
        float Bv = sB[cs * 17 + cn];
#pragma unroll
        for (int off = 1; off < 32; off <<= 1) {
            float ap = __shfl_up_sync(0xffffffffu, Av, off);
            float bp = __shfl_up_sync(0xffffffffu, Bv, off);
            if (cs >= off) { Bv = fmaf(Av, bp, Bv); Av *= ap; }
        }
        float hin = __shfl_up_sync(0xffffffffu, Bv, 1);
        sH[cs * 17 + cn] = (cs == 0) ? 0.0f : hin;
    }
    __syncthreads();

    // ---------- pass 2: fold C into hloc in place; butterfly; 1 atomic ----
    const float h_in = sH[seg * 17 + n];
    const bool b3 = (n & 8) != 0;
    const bool b2 = (n & 4) != 0;
    const bool b1 = (n & 2) != 0;
    const bool b0 = (n & 1) != 0;

#pragma unroll
    for (int j = 0; j < 16; j++)
        hloc[j] = fmaf(Pcum[j], h_in, hloc[j]) * Cp[j * 16];  // in-place, coalesced C

    // folded butterfly: lane n ends with sum over states at l = l0 + n
#pragma unroll
    for (int i = 0; i < 8; i++) {
        float mine = b3 ? hloc[i + 8] : hloc[i];
        float oth  = b3 ? hloc[i]     : hloc[i + 8];
        hloc[i] = mine + __shfl_xor_sync(0xffffffffu, oth, 8);
    }
#pragma unroll
    for (int i = 0; i < 4; i++) {
        float mine = b2 ? hloc[i + 4] : hloc[i];
        float oth  = b2 ? hloc[i]     : hloc[i + 4];
        hloc[i] = mine + __shfl_xor_sync(0xffffffffu, oth, 4);
    }
#pragma unroll
    for (int i = 0; i < 2; i++) {
        float mine = b1 ? hloc[i + 2] : hloc[i];
        float oth  = b1 ? hloc[i]     : hloc[i + 2];
        hloc[i] = mine + __shfl_xor_sync(0xffffffffu, oth, 2);
    }
    {
        float mine = b0 ? hloc[1] : hloc[0];
        float oth  = b0 ? hloc[0] : hloc[1];
        hloc[0] = mine + __shfl_xor_sync(0xffffffffu, oth, 1);
    }
    const int l = l0 + n;
    const int lmap = (k == 0) ? l : (511 - l);
    atomicAdd(&g_yb[b * 512 + lmap], wd * hloc[0]);
}

// ============================================================
// K4: gelu + LayerNorm over L per batch -> attn. PDL-synced.
// ============================================================
__global__ void ln_kernel(const float* __restrict__ ln_g,
                          const float* __restrict__ ln_b) {
    const int b = blockIdx.x;
    const int l = threadIdx.x;
    const float lg = ln_g[l];
    const float lb = ln_b[l];
    cudaGridDependencySynchronize();
    const float yb = gelu_exact(g_yb[b * 512 + l]);
    float s = yb, s2 = yb * yb;
#pragma unroll
    for (int o = 16; o; o >>= 1) {
        s += __shfl_xor_sync(0xffffffffu, s, o);
        s2 += __shfl_xor_sync(0xffffffffu, s2, o);
    }
    __shared__ float rs[16], rs2[16];
    __shared__ float smu, srv;
    const int w = l >> 5;
    if ((l & 31) == 0) { rs[w] = s; rs2[w] = s2; }
    __syncthreads();
    if (l == 0) {
        float S = 0.0f, S2 = 0.0f;
#pragma unroll
        for (int i = 0; i < 16; i++) { S += rs[i]; S2 += rs2[i]; }
        float mu = S * (1.0f / 512.0f);
        float var = S2 * (1.0f / 512.0f) - mu * mu;
        smu = mu;
        srv = rsqrtf(var + 1e-5f);
    }
    __syncthreads();
    g_attn[b * 512 + l] = (yb - smu) * srv * lg + lb;
}

// ============================================================
// K5: out v3 — PDL: prefetch x DURING ln, then sync, scale, store.
// ============================================================
__global__ void out_kernel(const float* __restrict__ x, float* __restrict__ out) {
    const int bc = blockIdx.x;
    const float4* __restrict__ xp = (const float4*)x + (size_t)bc * 1024;
    float4* __restrict__ op = (float4*)out + (size_t)bc * 1024;
    float4 v[4];
#pragma unroll
    for (int j = 0; j < 4; j++) v[j] = xp[j * 256 + threadIdx.x];
    cudaGridDependencySynchronize();
    const float a = 1.0f + g_attn[bc];
#pragma unroll
    for (int j = 0; j < 4; j++) {
        v[j].x *= a; v[j].y *= a; v[j].z *= a; v[j].w *= a;
        op[j * 256 + threadIdx.x] = v[j];
    }
}

// ---- host-side PDL launch helper ----
template <typename F, typename... Args>
static inline void launch_pdl(F f, dim3 grid, dim3 block, Args... args) {
    cudaLaunchConfig_t cfg = {};
    cfg.gridDim = grid;
    cfg.blockDim = block;
    cfg.dynamicSmemBytes = 0;
    cfg.stream = 0;
    cudaLaunchAttribute attr[1];
    attr[0].id = cudaLaunchAttributeProgrammaticStreamSerialization;
    attr[0].val.programmaticStreamSerializationAllowed = 1;
    cfg.attrs = attr;
    cfg.numAttrs = 1;
    cudaLaunchKernelEx(&cfg, f, args...);
}

extern "C" void kernel_launch(void* const* d_in, const int* in_sizes, int n_in,
                              void* d_out, int out_size) {
    const float* x      = (const float*)d_in[0];
    const float* xc_w   = (const float*)d_in[1];
    const float* dtc_w  = (const float*)d_in[2];
    const float* dtc_b  = (const float*)d_in[3];
    const float* Ac     = (const float*)d_in[4];
    const float* Dcs    = (const float*)d_in[5];
    const float* w_cin  = (const float*)d_in[6];
    const float* bn_g   = (const float*)d_in[7];
    const float* bn_b   = (const float*)d_in[8];
    const float* bn_m   = (const float*)d_in[9];
    const float* bn_v   = (const float*)d_in[10];
    const float* w_cout = (const float*)d_in[11];
    const float* ln_g   = (const float*)d_in[12];
    const float* ln_b   = (const float*)d_in[13];

    pool_kernel<<<B0 * C0, 256>>>(x);
    launch_pdl(prep_kernel, dim3(B0 * 2 * 8), dim3(256),
               xc_w, dtc_w, dtc_b, w_cin, bn_g, bn_b, bn_m, bn_v, Dcs, w_cout);
    launch_pdl(scan_kernel, dim3(2048), dim3(512), Ac, w_cout);
    launch_pdl(ln_kernel, dim3(B0), dim3(512), ln_g, ln_b);
    launch_pdl(out_kernel, dim3(B0 * C0), dim3(256), x, (float*)d_out);
}

// round 17
// speedup vs baseline: 1.0507x; 1.0330x over previous
#include <cuda_runtime.h>
#include <math.h>

#define B0 32
#define C0 512
#define HW 4096
#define DC 32
#define NS 16
#define RK 32
#define LL 512

// ---- global scratch (static device arrays; no runtime malloc) ----
__device__ float g_avg[B0 * C0];
__device__ float g_mx[B0 * C0];
__device__ float g_M[2 * DC * DC];           // fused dtc_w @ xc_w[:RK] (computed in pool)
__device__ float g_U[B0 * 2 * DC * LL];      // u layout [bk*32+d][l]
__device__ float g_Delta[B0 * 2 * DC * LL];  // post-softplus delta
__device__ float g_Bs[B0 * 2 * LL * NS];     // [bk][l][n]
__device__ float g_Cs[B0 * 2 * LL * NS];     // [bk][l][n]
__device__ float g_yb[B0 * LL];              // atomically accumulated sum_d w*y
__device__ float g_attn[B0 * C0];

__device__ __forceinline__ float gelu_exact(float v) {
    return 0.5f * v * (1.0f + erff(v * 0.70710678118654752f));
}
__device__ __forceinline__ float ex2_fast(float x) {
    float y;
    asm("ex2.approx.ftz.f32 %0, %1;" : "=f"(y) : "f"(x));
    return y;
}
__device__ __forceinline__ float softplus_fast(float a) {
    return fmaxf(a, 0.0f) + __logf(1.0f + __expf(-fabsf(a)));
}

// ============================================================
// K1: avg + max pool; zeroes g_yb; blocks 0..63 also compute the
//     weight fusion g_M (free compute inside an HBM-bound kernel).
// ============================================================
__global__ void pool_kernel(const float* __restrict__ x,
                            const float* __restrict__ dtc_w,
                            const float* __restrict__ xc_w) {
    int bc = blockIdx.x;
    if (threadIdx.x == 0) g_yb[bc] = 0.0f;   // grid == B0*C0 == elems of g_yb
    // wfuse: block bc<64 handles row (k,d) = (bc>>5, bc&31)
    if (bc < 64 && threadIdx.x < 32) {
        const int k = bc >> 5, d = bc & 31, dd = threadIdx.x;
        float a = 0.0f;
#pragma unroll
        for (int r = 0; r < 32; r++)
            a += dtc_w[k * 1024 + d * 32 + r] * xc_w[k * 2048 + r * 32 + dd];
        g_M[bc * 32 + dd] = a;
    }
    const float4* xp = (const float4*)(x + (size_t)bc * HW);
    float s = 0.0f, m = -INFINITY;
#pragma unroll
    for (int it = 0; it < 4; it++) {
        int i = it * 256 + threadIdx.x;
        float4 v = xp[i];
        s += (v.x + v.y) + (v.z + v.w);
        m = fmaxf(m, fmaxf(fmaxf(v.x, v.y), fmaxf(v.z, v.w)));
    }
#pragma unroll
    for (int o = 16; o; o >>= 1) {
        s += __shfl_xor_sync(0xffffffffu, s, o);
        m = fmaxf(m, __shfl_xor_sync(0xffffffffu, m, o));
    }
    __shared__ float ss[8], sm[8];
    int w = threadIdx.x >> 5;
    if ((threadIdx.x & 31) == 0) { ss[w] = s; sm[w] = m; }
    __syncthreads();
    if (threadIdx.x == 0) {
        float S = ss[0], M = sm[0];
#pragma unroll
        for (int i = 1; i < 8; i++) { S += ss[i]; M = fmaxf(M, sm[i]); }
        g_avg[bc] = S * (1.0f / (float)HW);
        g_mx[bc] = M;
    }
}

// ============================================================
// K2: prep v4 — 2-l register blocking. 256 blocks (bk x 4 groups
//     of 128 l's) x 256 thr; thread owns TWO l's, so each weight
//     LDS feeds 2 FMAs (halves phase-2 LDS). PDL-synced.
// ============================================================
__global__ void __launch_bounds__(256)
prep_kernel(const float* __restrict__ xc_w,
            const float* __restrict__ dtc_b,
            const float* __restrict__ w_cin,
            const float* __restrict__ bn_g,
            const float* __restrict__ bn_b,
            const float* __restrict__ bn_m,
            const float* __restrict__ bn_v,
            const float* __restrict__ Dcs,
            const float* __restrict__ w_cout) {
    const int bk = blockIdx.x >> 2;          // 0..63
    const int b = bk >> 1, k = bk & 1;
    const int l0 = (blockIdx.x & 3) << 7;    // 128 l's per block
    const int tid = threadIdx.x;
    const int myl = tid & 63;
    const int og = tid >> 6;                 // 0..3
    const int la = l0 + myl;                 // first owned l
    const int lb = l0 + 64 + myl;            // second owned l

    __shared__ float sWbc[1024];             // xc_w rows 32..63 (B then C)
    __shared__ float sM[1024];               // fused weights (from g_M)
    __shared__ float sU[128 * 33];           // padded u[l][d]
    __shared__ float sBC[128 * 17];          // padded B[l][n]
    __shared__ float sCC[128 * 17];          // padded C[l][n]
    __shared__ float sCin0[32], sCin1[32], sScale[32], sShift[32], sBias[32], sWD[32];

    // ---- pre-sync work (independent of pool outputs) ----
    for (int i = tid; i < 1024; i += 256) sWbc[i] = xc_w[k * 2048 + 1024 + i];
    if (tid < 32) {
        int d = tid;
        sCin0[d] = w_cin[d * 2 + 0];
        sCin1[d] = w_cin[d * 2 + 1];
        float sc = rsqrtf(bn_v[d] + 1e-5f) * bn_g[d];
        sScale[d] = sc;
        sShift[d] = bn_b[d] - bn_m[d] * sc;
        sBias[d] = dtc_b[k * 32 + d];
        sWD[d] = w_cout[d] * Dcs[k * 32 + d];
    }

    // ---- wait for pool (g_avg/g_mx AND g_M ready) ----
    cudaGridDependencySynchronize();

    for (int i = tid; i < 1024; i += 256) sM[i] = g_M[k * 1024 + i];

    // phase 1: u for 8 d's at BOTH owned l's
    const int ca = (k == 0) ? la : (511 - la);
    const int cb = (k == 0) ? lb : (511 - lb);
    {
        const float av_a = g_avg[b * 512 + ca], mv_a = g_mx[b * 512 + ca];
        const float av_b = g_avg[b * 512 + cb], mv_b = g_mx[b * 512 + cb];
#pragma unroll
        for (int i = 0; i < 8; i++) {
            const int d = og * 8 + i;
            float va = sCin0[d] * av_a + sCin1[d] * mv_a;
            va = gelu_exact(va * sScale[d] + sShift[d]);
            float vb = sCin0[d] * av_b + sCin1[d] * mv_b;
            vb = gelu_exact(vb * sScale[d] + sShift[d]);
            sU[myl * 33 + d] = va;
            sU[(myl + 64) * 33 + d] = vb;
            g_U[(bk * 32 + d) * LL + la] = va;
            g_U[(bk * 32 + d) * LL + lb] = vb;
        }
    }
    __syncthreads();

    // phase 2: both u vectors register-resident; 1 LDS per 2 FMA
    float ua[32], ub[32];
#pragma unroll
    for (int d = 0; d < 32; d++) {
        ua[d] = sU[myl * 33 + d];
        ub[d] = sU[(myl + 64) * 33 + d];
    }

    if (og < 2) {
#pragma unroll
        for (int i = 0; i < 16; i++) {
            const int d = og * 16 + i;
            float aa = sBias[d], ab = sBias[d];
#pragma unroll
            for (int dd = 0; dd < 32; dd++) {
                const float m = sM[d * 32 + dd];
                aa += ua[dd] * m;
                ab += ub[dd] * m;
            }
            g_Delta[(bk * 32 + d) * LL + la] = softplus_fast(aa);
            g_Delta[(bk * 32 + d) * LL + lb] = softplus_fast(ab);
        }
        if (og == 0) {
            float da = 0.0f, db = 0.0f;
#pragma unroll
            for (int d = 0; d < 32; d++) {
                da += sWD[d] * ua[d];
                db += sWD[d] * ub[d];
            }
            atomicAdd(&g_yb[b * 512 + ca], da);
            atomicAdd(&g_yb[b * 512 + cb], db);
        }
    } else if (og == 2) {
#pragma unroll
        for (int n = 0; n < 16; n++) {
            float aa = 0.0f, ab = 0.0f;
#pragma unroll
            for (int d = 0; d < 32; d++) {
                const float m = sWbc[n * 32 + d];
                aa += ua[d] * m;
                ab += ub[d] * m;
            }
            sBC[myl * 17 + n] = aa;
            sBC[(myl + 64) * 17 + n] = ab;
        }
    } else {
#pragma unroll
        for (int n = 0; n < 16; n++) {
            float aa = 0.0f, ab = 0.0f;
#pragma unroll
            for (int d = 0; d < 32; d++) {
                const float m = sWbc[(16 + n) * 32 + d];
                aa += ua[d] * m;
                ab += ub[d] * m;
            }
            sCC[myl * 17 + n] = aa;
            sCC[(myl + 64) * 17 + n] = ab;
        }
    }
    __syncthreads();

    // coalesced B/C stores (128 l x 16 n = 2048 each)
    const size_t base = ((size_t)bk * 512 + l0) * NS;
    for (int i = tid; i < 2048; i += 256) {
        const int li = i >> 4, ni = i & 15;
        g_Bs[base + i] = sBC[li * 17 + ni];
        g_Cs[base + i] = sCC[li * 17 + ni];
    }
}

// ============================================================
// K3: scan v7b — 512 threads/block, 32 segments x 16 steps,
//     conflict-free Kogge-Stone carry, in-place pass 2, one
//     atomic per thread. PDL-synced. (measured-best)
// ============================================================
__global__ void __launch_bounds__(512, 2)
scan_kernel(const float* __restrict__ Ac_logs,
            const float* __restrict__ w_cout) {
    const int tid = threadIdx.x;
    const int lane = tid & 31;
    const int half = lane >> 4;
    const int n = lane & 15;
    const int seg = (tid >> 5) * 2 + half;   // 0..31
    const int g = blockIdx.x;                // 0..2047
    const int kd = g & 63;
    const int k = kd >> 5;
    const int d = kd & 31;
    const int b = g >> 6;
    const int bkn = g >> 5;
    const int l0 = seg * 16;

    const float A = -__expf(Ac_logs[kd * NS + n]);
    const float cA = A * 1.4426950408889634f;
    const float wd = w_cout[d];

    cudaGridDependencySynchronize();

    const float* __restrict__ dp = g_Delta + (size_t)g * LL + l0;
    const float* __restrict__ up = g_U + (size_t)g * LL + l0;
    const float* __restrict__ Bp = g_Bs + (size_t)bkn * (LL * NS) + (size_t)l0 * NS + n;
    const float* __restrict__ Cp = g_Cs + (size_t)bkn * (LL * NS) + (size_t)l0 * NS + n;

    __shared__ float sA[32 * 17], sB[32 * 17], sH[32 * 17];  // padded: stride 17

    float hloc[16], Pcum[16];

    // ---------- pass 1: h_local and cumulative products ----------
    {
        float h = 0.0f, P = 1.0f;
#pragma unroll
        for (int c = 0; c < 2; c++) {
            float dl[8], ul[8], bv[8];
            const float4* dp4 = (const float4*)(dp + c * 8);
            const float4* up4 = (const float4*)(up + c * 8);
#pragma unroll
            for (int q = 0; q < 2; q++) {
                float4 t = dp4[q];
                dl[q * 4] = t.x; dl[q * 4 + 1] = t.y; dl[q * 4 + 2] = t.z; dl[q * 4 + 3] = t.w;
                float4 s = up4[q];
                ul[q * 4] = s.x; ul[q * 4 + 1] = s.y; ul[q * 4 + 2] = s.z; ul[q * 4 + 3] = s.w;
            }
            const float* bc = Bp + (size_t)c * 8 * NS;
#pragma unroll
            for (int j = 0; j < 8; j++) bv[j] = bc[j * 16];
#pragma unroll
            for (int j = 0; j < 8; j++) {
                const int jj = c * 8 + j;
                const float dBu = dl[j] * ul[j] * bv[j];
                const float dAj = ex2_fast(dl[j] * cA);
                h = fmaf(dAj, h, dBu);
                P *= dAj;
                hloc[jj] = h;
                Pcum[jj] = P;
            }
        }
        sA[seg * 17 + n] = P;
        sB[seg * 17 + n] = h;
    }
    __syncthreads();

    // ---------- carry: Kogge-Stone, warp w = state n=w ----------
    {
        const int cn = tid >> 5;
        const int cs = tid & 31;
        float Av = sA[cs * 17 + cn];
        float Bv = sB[cs * 17 + cn];
#pragma unroll
        for (int off = 1; off < 32; off <<= 1) {
            float ap = __shfl_up_sync(0xffffffffu, Av, off);
            float bp = __shfl_up_sync(0xffffffffu, Bv, off);
            if (cs >= off) { Bv = fmaf(Av, bp, Bv); Av *= ap; }
        }
        float hin = __shfl_up_sync(0xffffffffu, Bv, 1);
        sH[cs * 17 + cn] = (cs == 0) ? 0.0f : hin;
    }
    __syncthreads();

    // ---------- pass 2: fold C in place; butterfly; 1 atomic ----------
    const float h_in = sH[seg * 17 + n];
    const bool b3 = (n & 8) != 0;
    const bool b2 = (n & 4) != 0;
    const bool b1 = (n & 2) != 0;
    const bool b0 = (n & 1) != 0;

#pragma unroll
    for (int j = 0; j < 16; j++)
        hloc[j] = fmaf(Pcum[j], h_in, hloc[j]) * Cp[j * 16];

#pragma unroll
    for (int i = 0; i < 8; i++) {
        float mine = b3 ? hloc[i + 8] : hloc[i];
        float oth  = b3 ? hloc[i]     : hloc[i + 8];
        hloc[i] = mine + __shfl_xor_sync(0xffffffffu, oth, 8);
    }
#pragma unroll
    for (int i = 0; i < 4; i++) {
        float mine = b2 ? hloc[i + 4] : hloc[i];
        float oth  = b2 ? hloc[i]     : hloc[i + 4];
        hloc[i] = mine + __shfl_xor_sync(0xffffffffu, oth, 4);
    }
#pragma unroll
    for (int i = 0; i < 2; i++) {
        float mine = b1 ? hloc[i + 2] : hloc[i];
        float oth  = b1 ? hloc[i]     : hloc[i + 2];
        hloc[i] = mine + __shfl_xor_sync(0xffffffffu, oth, 2);
    }
    {
        float mine = b0 ? hloc[1] : hloc[0];
        float oth  = b0 ? hloc[0] : hloc[1];
        hloc[0] = mine + __shfl_xor_sync(0xffffffffu, oth, 1);
    }
    const int l = l0 + n;
    const int lmap = (k == 0) ? l : (511 - l);
    atomicAdd(&g_yb[b * 512 + lmap], wd * hloc[0]);
}

// ============================================================
// K4: gelu + LayerNorm over L per batch -> attn. PDL-synced.
// ============================================================
__global__ void ln_kernel(const float* __restrict__ ln_g,
                          const float* __restrict__ ln_b) {
    const int b = blockIdx.x;
    const int l = threadIdx.x;
    const float lg = ln_g[l];
    const float lb = ln_b[l];
    cudaGridDependencySynchronize();
    const float yb = gelu_exact(g_yb[b * 512 + l]);
    float s = yb, s2 = yb * yb;
#pragma unroll
    for (int o = 16; o; o >>= 1) {
        s += __shfl_xor_sync(0xffffffffu, s, o);
        s2 += __shfl_xor_sync(0xffffffffu, s2, o);
    }
    __shared__ float rs[16], rs2[16];
    __shared__ float smu, srv;
    const int w = l >> 5;
    if ((l & 31) == 0) { rs[w] = s; rs2[w] = s2; }
    __syncthreads();
    if (l == 0) {
        float S = 0.0f, S2 = 0.0f;
#pragma unroll
        for (int i = 0; i < 16; i++) { S += rs[i]; S2 += rs2[i]; }
        float mu = S * (1.0f / 512.0f);
        float var = S2 * (1.0f / 512.0f) - mu * mu;
        smu = mu;
        srv = rsqrtf(var + 1e-5f);
    }
    __syncthreads();
    g_attn[b * 512 + l] = (yb - smu) * srv * lg + lb;
}

// ============================================================
// K5: out v3 — PDL: prefetch x DURING ln, then sync, scale, store.
// ============================================================
__global__ void out_kernel(const float* __restrict__ x, float* __restrict__ out) {
    const int bc = blockIdx.x;
    const float4* __restrict__ xp = (const float4*)x + (size_t)bc * 1024;
    float4* __restrict__ op = (float4*)out + (size_t)bc * 1024;
    float4 v[4];
#pragma unroll
    for (int j = 0; j < 4; j++) v[j] = xp[j * 256 + threadIdx.x];
    cudaGridDependencySynchronize();
    const float a = 1.0f + g_attn[bc];
#pragma unroll
    for (int j = 0; j < 4; j++) {
        v[j].x *= a; v[j].y *= a; v[j].z *= a; v[j].w *= a;
        op[j * 256 + threadIdx.x] = v[j];
    }
}

// ---- host-side PDL launch helper ----
template <typename F, typename... Args>
static inline void launch_pdl(F f, dim3 grid, dim3 block, Args... args) {
    cudaLaunchConfig_t cfg = {};
    cfg.gridDim = grid;
    cfg.blockDim = block;
    cfg.dynamicSmemBytes = 0;
    cfg.stream = 0;
    cudaLaunchAttribute attr[1];
    attr[0].id = cudaLaunchAttributeProgrammaticStreamSerialization;
    attr[0].val.programmaticStreamSerializationAllowed = 1;
    cfg.attrs = attr;
    cfg.numAttrs = 1;
    cudaLaunchKernelEx(&cfg, f, args...);
}

extern "C" void kernel_launch(void* const* d_in, const int* in_sizes, int n_in,
                              void* d_out, int out_size) {
    const float* x      = (const float*)d_in[0];
    const float* xc_w   = (const float*)d_in[1];
    const float* dtc_w  = (const float*)d_in[2];
    const float* dtc_b  = (const float*)d_in[3];
    const float* Ac     = (const float*)d_in[4];
    const float* Dcs    = (const float*)d_in[5];
    const float* w_cin  = (const float*)d_in[6];
    const float* bn_g   = (const float*)d_in[7];
    const float* bn_b   = (const float*)d_in[8];
    const float* bn_m   = (const float*)d_in[9];
    const float* bn_v   = (const float*)d_in[10];
    const float* w_cout = (const float*)d_in[11];
    const float* ln_g   = (const float*)d_in[12];
    const float* ln_b   = (const float*)d_in[13];

    pool_kernel<<<B0 * C0, 256>>>(x, dtc_w, xc_w);
    launch_pdl(prep_kernel, dim3(B0 * 2 * 4), dim3(256),
               xc_w, dtc_b, w_cin, bn_g, bn_b, bn_m, bn_v, Dcs, w_cout);
    launch_pdl(scan_kernel, dim3(2048), dim3(512), Ac, w_cout);
    launch_pdl(ln_kernel, dim3(B0), dim3(512), ln_g, ln_b);
    launch_pdl(out_kernel, dim3(B0 * C0), dim3(256), x, (float*)d_out);
}